// round 17
// baseline (speedup 1.0000x reference)
#include <cuda_runtime.h>
#include <cuda_fp16.h>
#include <cuda_bf16.h>
#include <stdint.h>
#include <math.h>

#define N_ATOMS 100000
#define M_NBR   12
#define F_DIM   64
#define C_DIM   128
#define KW      192
#define P_ROWS  (N_ATOMS * M_NBR)  // 1200000
#define BN_EPS  1e-5f
#define NWTILES (P_ROWS / 32)      // 37500
#define NATILES (N_ATOMS / 32)     // 3125

typedef unsigned long long u64;

// ---------------- scratch ----------------
__device__ __align__(256) float  g_S [N_ATOMS * C_DIM];
__device__ __align__(256) float  g_P [N_ATOMS * C_DIM];
__device__ __align__(256) __half g_Zh[(size_t)P_ROWS * C_DIM];
__device__ __align__(256) float  g_NS[N_ATOMS * F_DIM];
__device__ __align__(256) __nv_bfloat16 g_Wh[C_DIM * 64];
__device__ __align__(256) __nv_bfloat16 g_Wl[C_DIM * 64];
__device__ float g_stats1[2 * C_DIM];
__device__ float g_stats2[2 * F_DIM];
__device__ float g_aff1 [2 * C_DIM];
__device__ float g_aff2 [2 * F_DIM];

// ---------------- helpers ----------------
__device__ __forceinline__ float tanh_fast(float x) {
    float y; asm("tanh.approx.f32 %0, %1;" : "=f"(y) : "f"(x)); return y;
}
__device__ __forceinline__ float sigmoid_fast(float x) {
    return fmaf(0.5f, tanh_fast(0.5f * x), 0.5f);
}
__device__ __forceinline__ float softplus_fast(float x) {
    return fmaxf(x, 0.f) + __logf(1.f + __expf(-fabsf(x)));
}
__device__ __forceinline__ uint32_t smem_u32(const void* p) {
    uint32_t a;
    asm("{ .reg .u64 t; cvta.to.shared.u64 t, %1; cvt.u32.u64 %0, t; }" : "=r"(a) : "l"(p));
    return a;
}
#define SWZ(b) ((b) ^ (((b) >> 3) & 0x70))

__device__ __forceinline__ void ldsm4(uint32_t* r, uint32_t addr) {
    asm volatile("ldmatrix.sync.aligned.m8n8.x4.shared.b16 {%0,%1,%2,%3}, [%4];"
        : "=r"(r[0]), "=r"(r[1]), "=r"(r[2]), "=r"(r[3]) : "r"(addr));
}
__device__ __forceinline__ void mma_bf16(float* d, const uint32_t* a, const uint32_t* b) {
    asm volatile("mma.sync.aligned.m16n8k16.row.col.f32.bf16.bf16.f32 "
        "{%0,%1,%2,%3}, {%4,%5,%6,%7}, {%8,%9}, {%0,%1,%2,%3};"
        : "+f"(d[0]), "+f"(d[1]), "+f"(d[2]), "+f"(d[3])
        : "r"(a[0]), "r"(a[1]), "r"(a[2]), "r"(a[3]), "r"(b[0]), "r"(b[1]));
}
__device__ __forceinline__ void split_bf16x2(float x, float y,
                                             uint32_t& hi, uint32_t& lo) {
    __nv_bfloat162 h, l;
    h.x = __float2bfloat16(x); h.y = __float2bfloat16(y);
    l.x = __float2bfloat16(x - __bfloat162float(h.x));
    l.y = __float2bfloat16(y - __bfloat162float(h.y));
    hi = *(uint32_t*)&h; lo = *(uint32_t*)&l;
}

__global__ void knop() {}

// ============ K1: HMMA S,P precompute (full hi/lo split) ============
#define K1_B_HI 0
#define K1_B_LO 32768
#define K1_A    65536
#define K1_TOT  98304

__global__ __launch_bounds__(128, 2) void k1_hmma(
        const float* __restrict__ atom, const float* __restrict__ W,
        const float* __restrict__ b) {
    extern __shared__ __align__(1024) unsigned char SB[];
    const uint32_t sbase = smem_u32(SB);
    const int tid = threadIdx.x, wid = tid >> 5, lane = tid & 31;

    if (blockIdx.x == 0) {
        if (tid < 128) { g_stats1[tid] = 0.f; g_stats1[128 + tid] = 0.f; }
        if (tid < 64)  { g_stats2[tid] = 0.f; g_stats2[64  + tid] = 0.f; }
        for (int i = tid; i < C_DIM * 64; i += 128) {
            int c = i >> 6, k = i & 63;
            float x = W[c * KW + 128 + k];
            __nv_bfloat16 hi = __float2bfloat16(x);
            __nv_bfloat16 lo = __float2bfloat16(x - __bfloat162float(hi));
            g_Wh[i] = hi; g_Wl[i] = lo;
        }
    }

    for (int i = tid; i < 256 * 8; i += 128) {
        int c = i >> 3, u = i & 7;
        const float* src = (c < 128) ? &W[c * KW + u * 8]
                                     : &W[(c - 128) * KW + 64 + u * 8];
        float4 va = *(const float4*)src;
        float4 vb = *(const float4*)(src + 4);
        uint4 hi4, lo4;
        split_bf16x2(va.x, va.y, hi4.x, lo4.x);
        split_bf16x2(va.z, va.w, hi4.y, lo4.y);
        split_bf16x2(vb.x, vb.y, hi4.z, lo4.z);
        split_bf16x2(vb.z, vb.w, hi4.w, lo4.w);
        uint32_t sw = SWZ((uint32_t)(c * 128 + u * 16));
        *(uint4*)(SB + K1_B_HI + sw) = hi4;
        *(uint4*)(SB + K1_B_LO + sw) = lo4;
    }
    __syncthreads();

    const int g    = lane >> 2, cq = lane & 3;
    const int sel  = lane >> 3;
    const int rsel = ((sel & 1) << 3) | (lane & 7);
    const int ksel = (sel >> 1) << 4;
    const int nsel = ((sel >> 1) << 3) | (lane & 7);
    const int kselB = (sel & 1) << 4;
    unsigned char* aW = SB + K1_A + (wid << 13);
    const uint32_t aBase = sbase + K1_A + (wid << 13);

    for (int wt = blockIdx.x * 4 + wid; wt < NATILES; wt += gridDim.x * 4) {
        const int n0 = wt * 32;

        #pragma unroll
        for (int pass = 0; pass < 4; ++pass) {
            int r  = pass * 8 + g;
            int c0 = cq * 16;
            #pragma unroll
            for (int q = 0; q < 4; ++q) {
                float4 v = *(const float4*)&atom[(size_t)(n0 + r) * 64 + c0 + q * 4];
                uint2 sh, sl;
                split_bf16x2(v.x, v.y, sh.x, sl.x);
                split_bf16x2(v.z, v.w, sh.y, sl.y);
                uint32_t sw = SWZ((uint32_t)(r * 128 + (c0 + q * 4) * 2));
                *(uint2*)(aW + sw)        = sh;
                *(uint2*)(aW + 4096 + sw) = sl;
            }
        }
        __syncwarp();

        #pragma unroll
        for (int chunk = 0; chunk < 4; ++chunk) {
            float acc[2][8][4];
            #pragma unroll
            for (int mf = 0; mf < 2; ++mf)
                #pragma unroll
                for (int nf = 0; nf < 8; ++nf)
                    #pragma unroll
                    for (int e = 0; e < 4; ++e) acc[mf][nf][e] = 0.f;

            #pragma unroll
            for (int ks = 0; ks < 4; ++ks) {
                uint32_t Ah[2][4], Al[2][4];
                #pragma unroll
                for (int mf = 0; mf < 2; ++mf) {
                    uint32_t byteA = (uint32_t)((mf * 16 + rsel) * 128 + ks * 32 + ksel);
                    ldsm4(Ah[mf], aBase + SWZ(byteA));
                    ldsm4(Al[mf], aBase + 4096 + SWZ(byteA));
                }
                #pragma unroll
                for (int q = 0; q < 4; ++q) {
                    uint32_t byteB = (uint32_t)((chunk * 64 + q * 16 + nsel) * 128 + ks * 32 + kselB);
                    uint32_t Bh[4], Bl[4];
                    ldsm4(Bh, sbase + K1_B_HI + SWZ(byteB));
                    ldsm4(Bl, sbase + K1_B_LO + SWZ(byteB));
                    #pragma unroll
                    for (int mf = 0; mf < 2; ++mf) {
                        mma_bf16(acc[mf][q*2],   Ah[mf], Bh);
                        mma_bf16(acc[mf][q*2],   Ah[mf], Bl);
                        mma_bf16(acc[mf][q*2],   Al[mf], Bh);
                        mma_bf16(acc[mf][q*2+1], Ah[mf], Bh + 2);
                        mma_bf16(acc[mf][q*2+1], Ah[mf], Bl + 2);
                        mma_bf16(acc[mf][q*2+1], Al[mf], Bh + 2);
                    }
                }
            }

            float* dst = (chunk < 2) ? g_S : g_P;
            const int cbase = (chunk & 1) * 64;
            #pragma unroll
            for (int nf = 0; nf < 8; ++nf) {
                int c = cbase + nf * 8 + cq * 2;
                float b0 = 0.f, b1 = 0.f;
                if (chunk < 2) {
                    float2 bv = *(const float2*)&b[c];
                    b0 = bv.x; b1 = bv.y;
                }
                #pragma unroll
                for (int mf = 0; mf < 2; ++mf)
                    #pragma unroll
                    for (int rr = 0; rr < 2; ++rr) {
                        int n = n0 + mf * 16 + rr * 8 + g;
                        float2 o;
                        o.x = acc[mf][nf][rr*2]   + b0;
                        o.y = acc[mf][nf][rr*2+1] + b1;
                        *(float2*)&dst[(size_t)n * C_DIM + c] = o;
                    }
            }
        }
        __syncwarp();
    }
}

// k2 smem layout (dynamic, 48KB): B hi only
#define SM_B_HI 0
#define SM_A_HI 16384          // + wid*4096
#define SM_E    32768          // + wid*4096
#define SM_TOT  49152

// ---------------- K2: HMMA (A-hi x B-hi) + fp16 E + gather + BN1 stats -----
// occupancy experiment: 4 CTAs/SM (128-reg cap; spills traded for +33% warps)
__global__ __launch_bounds__(128, 4) void k2_hmma(
        const float* __restrict__ nbr, const int* __restrict__ idx) {
    extern __shared__ __align__(1024) unsigned char SB[];
    const uint32_t sbase = smem_u32(SB);
    const int tid = threadIdx.x, wid = tid >> 5, lane = tid & 31;

    for (int i = tid; i < 128 * 8; i += 128) {
        int c = i >> 3, u = i & 7;
        uint32_t sw = SWZ((uint32_t)(c * 128 + u * 16));
        *(uint4*)(SB + SM_B_HI + sw) = *(const uint4*)&g_Wh[c * 64 + u * 8];
    }
    __syncthreads();

    const int g    = lane >> 2, cq = lane & 3;
    const int sel  = lane >> 3;
    const int rsel = ((sel & 1) << 3) | (lane & 7);
    const int ksel = (sel >> 1) << 4;
    const int nsel = ((sel >> 1) << 3) | (lane & 7);
    const int kselB = (sel & 1) << 4;
    unsigned char* aHi = SB + SM_A_HI + (wid << 12);
    const uint32_t aBaseHi = sbase + SM_A_HI + (wid << 12);
    const uint32_t eBase   = sbase + SM_E    + (wid << 12);

    float lsum[2][16], lsq[2][16];
    #pragma unroll
    for (int h = 0; h < 2; ++h)
        #pragma unroll
        for (int i = 0; i < 16; ++i) { lsum[h][i] = 0.f; lsq[h][i] = 0.f; }

    for (int wt = blockIdx.x * 4 + wid; wt < NWTILES; wt += gridDim.x * 4) {
        const int p0 = wt * 32;

        #pragma unroll
        for (int pass = 0; pass < 4; ++pass) {
            int r  = pass * 8 + g;
            int c0 = cq * 16;
            #pragma unroll
            for (int q = 0; q < 4; ++q) {
                float4 v = __ldcs((const float4*)&nbr[(size_t)(p0 + r) * 64 + c0 + q * 4]);
                __nv_bfloat162 h0, h1;
                h0.x = __float2bfloat16(v.x); h0.y = __float2bfloat16(v.y);
                h1.x = __float2bfloat16(v.z); h1.y = __float2bfloat16(v.w);
                uint32_t sw = SWZ((uint32_t)(r * 128 + (c0 + q * 4) * 2));
                uint2 sh;
                sh.x = *(uint32_t*)&h0; sh.y = *(uint32_t*)&h1;
                *(uint2*)(aHi + sw) = sh;
            }
        }
        __syncwarp();

        uint32_t Af[4][2][4];
        #pragma unroll
        for (int ks = 0; ks < 4; ++ks)
            #pragma unroll
            for (int mf = 0; mf < 2; ++mf) {
                uint32_t byteA = (uint32_t)((mf * 16 + rsel) * 128 + ks * 32 + ksel);
                ldsm4(Af[ks][mf], aBaseHi + SWZ(byteA));
            }

        #pragma unroll
        for (int h = 0; h < 2; ++h) {
            float acc[2][8][4];
            #pragma unroll
            for (int mf = 0; mf < 2; ++mf)
                #pragma unroll
                for (int nf = 0; nf < 8; ++nf)
                    #pragma unroll
                    for (int e = 0; e < 4; ++e) acc[mf][nf][e] = 0.f;

            #pragma unroll
            for (int ks = 0; ks < 4; ++ks) {
                #pragma unroll
                for (int q = 0; q < 4; ++q) {
                    uint32_t byteB = (uint32_t)((h * 64 + q * 16 + nsel) * 128 + ks * 32 + kselB);
                    uint32_t Bh[4];
                    ldsm4(Bh, sbase + SM_B_HI + SWZ(byteB));
                    #pragma unroll
                    for (int mf = 0; mf < 2; ++mf) {
                        mma_bf16(acc[mf][q*2],   Af[ks][mf], Bh);
                        mma_bf16(acc[mf][q*2+1], Af[ks][mf], Bh + 2);
                    }
                }
            }

            #pragma unroll
            for (int mf = 0; mf < 2; ++mf)
                #pragma unroll
                for (int nf = 0; nf < 8; ++nf)
                    #pragma unroll
                    for (int rr = 0; rr < 2; ++rr) {
                        int r = mf * 16 + rr * 8 + g;
                        int c = nf * 8 + cq * 2;
                        __half2 hv = __floats2half2_rn(acc[mf][nf][rr*2], acc[mf][nf][rr*2+1]);
                        uint32_t byte = ((uint32_t)c * 2) ^ (((uint32_t)r & 7) << 4);
                        uint32_t addr = eBase + (uint32_t)r * 128 + byte;
                        asm volatile("st.shared.b32 [%0], %1;" ::
                            "r"(addr), "r"(*(uint32_t*)&hv));
                    }
            __syncwarp();

            #pragma unroll
            for (int pass = 0; pass < 4; ++pass) {
                int r = pass * 8 + g;
                int p = p0 + r;
                int n = p / 12;
                int j = __ldg(&idx[p]);
                int cpart = cq * 16;
                float z[16];
                #pragma unroll
                for (int half16 = 0; half16 < 2; ++half16) {
                    uint32_t byte = (((uint32_t)(cpart + half16 * 8) * 2)) ^ (((uint32_t)r & 7) << 4);
                    uint32_t a0, a1, a2, a3;
                    asm volatile("ld.shared.v4.b32 {%0,%1,%2,%3}, [%4];"
                        : "=r"(a0), "=r"(a1), "=r"(a2), "=r"(a3)
                        : "r"(eBase + (uint32_t)r * 128 + byte));
                    float2 e0 = __half22float2(*(__half2*)&a0);
                    float2 e1 = __half22float2(*(__half2*)&a1);
                    float2 e2 = __half22float2(*(__half2*)&a2);
                    float2 e3 = __half22float2(*(__half2*)&a3);
                    float4 s0 = *(const float4*)&g_S[(size_t)n * C_DIM + h * 64 + cpart + half16 * 8];
                    float4 s1 = *(const float4*)&g_S[(size_t)n * C_DIM + h * 64 + cpart + half16 * 8 + 4];
                    float4 p0v = *(const float4*)&g_P[(size_t)j * C_DIM + h * 64 + cpart + half16 * 8];
                    float4 p1v = *(const float4*)&g_P[(size_t)j * C_DIM + h * 64 + cpart + half16 * 8 + 4];
                    int o = half16 * 8;
                    z[o+0] = e0.x + s0.x + p0v.x;  z[o+1] = e0.y + s0.y + p0v.y;
                    z[o+2] = e1.x + s0.z + p0v.z;  z[o+3] = e1.y + s0.w + p0v.w;
                    z[o+4] = e2.x + s1.x + p1v.x;  z[o+5] = e2.y + s1.y + p1v.y;
                    z[o+6] = e3.x + s1.z + p1v.z;  z[o+7] = e3.y + s1.w + p1v.w;
                }
                #pragma unroll
                for (int e = 0; e < 16; ++e) {
                    lsum[h][e] += z[e];
                    lsq[h][e]  = fmaf(z[e], z[e], lsq[h][e]);
                }
                uint4 st0, st1;
                {
                    __half2 a0 = __floats2half2_rn(z[0],  z[1]);
                    __half2 a1 = __floats2half2_rn(z[2],  z[3]);
                    __half2 a2 = __floats2half2_rn(z[4],  z[5]);
                    __half2 a3 = __floats2half2_rn(z[6],  z[7]);
                    __half2 a4 = __floats2half2_rn(z[8],  z[9]);
                    __half2 a5 = __floats2half2_rn(z[10], z[11]);
                    __half2 a6 = __floats2half2_rn(z[12], z[13]);
                    __half2 a7 = __floats2half2_rn(z[14], z[15]);
                    st0.x = *(uint32_t*)&a0; st0.y = *(uint32_t*)&a1;
                    st0.z = *(uint32_t*)&a2; st0.w = *(uint32_t*)&a3;
                    st1.x = *(uint32_t*)&a4; st1.y = *(uint32_t*)&a5;
                    st1.z = *(uint32_t*)&a6; st1.w = *(uint32_t*)&a7;
                }
                __stcs((uint4*)&g_Zh[(size_t)p * C_DIM + h * 64 + cpart],     st0);
                __stcs((uint4*)&g_Zh[(size_t)p * C_DIM + h * 64 + cpart + 8], st1);
            }
            __syncwarp();
        }
    }

    __syncthreads();
    float* st = (float*)SB;
    for (int i = tid; i < 512; i += 128) st[i] = 0.f;
    __syncthreads();
    #pragma unroll
    for (int h = 0; h < 2; ++h)
        #pragma unroll
        for (int e = 0; e < 16; ++e) {
            int ch = h * 64 + cq * 16 + e;
            atomicAdd(&st[ch],       lsum[h][e]);
            atomicAdd(&st[256 + ch], lsq[h][e]);
        }
    __syncthreads();
    if (tid < 128) {
        atomicAdd(&g_stats1[tid],       st[tid]);
        atomicAdd(&g_stats1[128 + tid], st[256 + tid]);
    }
}

// ---------------- K3 ----------------
__global__ void k3_aff1(const float* __restrict__ gamma1,
                        const float* __restrict__ beta1) {
    int c = threadIdx.x;
    float inv  = 1.f / (float)P_ROWS;
    float mean = g_stats1[c] * inv;
    float var  = g_stats1[128 + c] * inv - mean * mean;
    float sc   = gamma1[c] * rsqrtf(var + BN_EPS);
    g_aff1[c]       = sc;
    g_aff1[128 + c] = beta1[c] - mean * sc;
}

// ---------------- K4: 8-channel threads, uint4 streaming loads -------------
__global__ __launch_bounds__(256) void k4_reduce(const float* __restrict__ bw) {
    __shared__ float sSum[64], sSq[64];
    const int tid = threadIdx.x;
    if (tid < 64) { sSum[tid] = 0.f; sSq[tid] = 0.f; }
    __syncthreads();
    const int c8 = (tid & 7) * 8;
    const int al = tid >> 3;
    float sc1[8], sh1[8], sc2[8], sh2[8];
    #pragma unroll
    for (int e = 0; e < 8; ++e) {
        sc1[e] = g_aff1[c8 + e];       sh1[e] = g_aff1[128 + c8 + e];
        sc2[e] = g_aff1[64 + c8 + e];  sh2[e] = g_aff1[192 + c8 + e];
    }
    float lsum[8], lsq[8];
    #pragma unroll
    for (int e = 0; e < 8; ++e) { lsum[e] = 0.f; lsq[e] = 0.f; }

    for (int n = blockIdx.x * 32 + al; n < N_ATOMS; n += gridDim.x * 32) {
        float acc[8];
        #pragma unroll
        for (int e = 0; e < 8; ++e) acc[e] = 0.f;
        #pragma unroll
        for (int m = 0; m < 12; m++) {
            size_t base = (size_t)(n * 12 + m) * C_DIM;
            uint4 hf = __ldcs((const uint4*)&g_Zh[base + c8]);
            uint4 hc = __ldcs((const uint4*)&g_Zh[base + 64 + c8]);
            float w  = __ldg(&bw[n * 12 + m]);
            float w2 = w * w;
            float2 f0 = __half22float2(*(__half2*)&hf.x);
            float2 f1 = __half22float2(*(__half2*)&hf.y);
            float2 f2 = __half22float2(*(__half2*)&hf.z);
            float2 f3 = __half22float2(*(__half2*)&hf.w);
            float2 c0 = __half22float2(*(__half2*)&hc.x);
            float2 c1 = __half22float2(*(__half2*)&hc.y);
            float2 c2 = __half22float2(*(__half2*)&hc.z);
            float2 c3 = __half22float2(*(__half2*)&hc.w);
            float zf[8] = { f0.x, f0.y, f1.x, f1.y, f2.x, f2.y, f3.x, f3.y };
            float zc[8] = { c0.x, c0.y, c1.x, c1.y, c2.x, c2.y, c3.x, c3.y };
            #pragma unroll
            for (int e = 0; e < 8; ++e) {
                float z1 = fmaf(zf[e], sc1[e], sh1[e]);
                float z2 = fmaf(zc[e], sc2[e], sh2[e]);
                acc[e] = fmaf(w2 * sigmoid_fast(z1), softplus_fast(z2), acc[e]);
            }
        }
        float4 o0, o1;
        o0.x = acc[0]; o0.y = acc[1]; o0.z = acc[2]; o0.w = acc[3];
        o1.x = acc[4]; o1.y = acc[5]; o1.z = acc[6]; o1.w = acc[7];
        *(float4*)&g_NS[n * 64 + c8]     = o0;
        *(float4*)&g_NS[n * 64 + c8 + 4] = o1;
        #pragma unroll
        for (int e = 0; e < 8; ++e) {
            lsum[e] += acc[e];
            lsq[e]  = fmaf(acc[e], acc[e], lsq[e]);
        }
    }
    #pragma unroll
    for (int e = 0; e < 8; ++e) {
        atomicAdd(&sSum[c8 + e], lsum[e]);
        atomicAdd(&sSq[c8 + e],  lsq[e]);
    }
    __syncthreads();
    if (tid < 64) {
        atomicAdd(&g_stats2[tid],      sSum[tid]);
        atomicAdd(&g_stats2[64 + tid], sSq[tid]);
    }
}

// ---------------- K5 ----------------
__global__ void k5_aff2(const float* __restrict__ gamma2,
                        const float* __restrict__ beta2) {
    int f = threadIdx.x;
    float inv  = 1.f / (float)N_ATOMS;
    float mean = g_stats2[f] * inv;
    float var  = g_stats2[64 + f] * inv - mean * mean;
    float sc   = gamma2[f] * rsqrtf(var + BN_EPS);
    g_aff2[f]      = sc;
    g_aff2[64 + f] = beta2[f] - mean * sc;
}

// ---------------- K6 ----------------
__global__ void k6_out(const float* __restrict__ atom, float* __restrict__ out) {
    int i = blockIdx.x * blockDim.x + threadIdx.x;
    if (i < N_ATOMS * F_DIM) {
        int f = i & 63;
        float x = atom[i] + fmaf(g_NS[i], g_aff2[f], g_aff2[64 + f]);
        out[i] = softplus_fast(x);
    }
}

// ---------------- launch ----------------
extern "C" void kernel_launch(void* const* d_in, const int* in_sizes, int n_in,
                              void* d_out, int out_size) {
    const float* atom   = (const float*)d_in[0];
    const float* nbr    = (const float*)d_in[1];
    const float* bw     = (const float*)d_in[2];
    const int*   idx    = (const int*)  d_in[3];
    const float* W      = (const float*)d_in[4];
    const float* b      = (const float*)d_in[5];
    const float* gamma1 = (const float*)d_in[6];
    const float* beta1  = (const float*)d_in[7];
    const float* gamma2 = (const float*)d_in[8];
    const float* beta2  = (const float*)d_in[9];
    float* out = (float*)d_out;

    cudaFuncSetAttribute(k1_hmma, cudaFuncAttributeMaxDynamicSharedMemorySize, K1_TOT);
    cudaFuncSetAttribute(k2_hmma, cudaFuncAttributeMaxDynamicSharedMemorySize, SM_TOT);

    knop<<<1, 32>>>();
    knop<<<1, 32>>>();
    k1_hmma<<<444, 128, K1_TOT>>>(atom, W, b);
    k2_hmma<<<592, 128, SM_TOT>>>(nbr, idx);
    k3_aff1<<<1, 128>>>(gamma1, beta1);
    k4_reduce<<<592, 256>>>(bw);
    k5_aff2<<<1, 64>>>(gamma2, beta2);
    k6_out<<<(N_ATOMS * F_DIM + 255) / 256, 256>>>(atom, out);
}